// round 5
// baseline (speedup 1.0000x reference)
#include <cuda_runtime.h>
#include <math.h>

#define DDIM   256
#define BATCH  128
#define SEQ    1024
#define NROWS  (BATCH*SEQ)          // 131072
#define QROWS  (NROWS/4)            // 32768
#define NBLK_B 512
#define NBLK_C 2048

// ---- scratch (static device globals; no allocation) ----
__device__ __align__(16) float g_part[8*BATCH*DDIM];   // pass-A partial sums [j][b][d]
__device__ __align__(16) float g_cb[BATCH*DDIM];       // per-batch centroids
__device__ __align__(16) float g_mean[DDIM];
__device__ float g_ic;                                  // 1/(1+mean0)
__device__ __align__(16) float g_bpS[NBLK_B*DDIM];     // pass-B per-block sum(t)
__device__ __align__(16) float g_bpQ[NBLK_B*DDIM];     // pass-B per-block sum(t^2)
__device__ __align__(16) float g_scale[DDIM];          // gamma / sqrt(var+eps)
__device__ float g_ib;                                  // 1/(1+beta0)
__device__ float g_lab;                                 // linner(ab,ab) = -2(1+beta0)

__device__ __forceinline__ float warpsum(float v) {
    #pragma unroll
    for (int off = 16; off > 0; off >>= 1)
        v += __shfl_xor_sync(0xffffffffu, v, off);
    return v;
}

__device__ __forceinline__ void warpsum2(float& a, float& b) {
    #pragma unroll
    for (int off = 16; off > 0; off >>= 1) {
        a += __shfl_xor_sync(0xffffffffu, a, off);
        b += __shfl_xor_sync(0xffffffffu, b, off);
    }
}

__device__ __forceinline__ void warpsum4(float& a, float& b, float& c, float& d) {
    #pragma unroll
    for (int off = 16; off > 0; off >>= 1) {
        a += __shfl_xor_sync(0xffffffffu, a, off);
        b += __shfl_xor_sync(0xffffffffu, b, off);
        c += __shfl_xor_sync(0xffffffffu, c, off);
        d += __shfl_xor_sync(0xffffffffu, d, off);
    }
}

__device__ __forceinline__ float blocksum256(float v, float* sh) {
    const int lane = threadIdx.x & 31;
    const int warp = threadIdx.x >> 5;
    float w = warpsum(v);
    if (lane == 0) sh[warp] = w;
    __syncthreads();
    float r = sh[0];
    #pragma unroll
    for (int i = 1; i < 8; i++) r += sh[i];
    return r;
}

// fast f = acosh(alpha)/sqrt(alpha^2-1)
__device__ __forceinline__ float acosh_over_s(float alpha) {
    float a2m1 = fmaf(alpha, alpha, -1.0f);
    float r = rsqrtf(a2m1);
    float s = a2m1 * r;
    return __logf(alpha + s) * r;
}

// ---------------------------------------------------------------------------
// Pass A: per-(chunk j, batch b) feature sums over 128 rows of S.
// ---------------------------------------------------------------------------
__global__ void __launch_bounds__(256) passA_kernel(const float* __restrict__ x) {
    const int j = blockIdx.x;
    const int b = blockIdx.y;
    const int d = threadIdx.x;
    const float* p = x + ((size_t)b*SEQ + (size_t)j*128) * DDIM + d;
    float a0=0.f,a1=0.f,a2=0.f,a3=0.f,a4=0.f,a5=0.f,a6=0.f,a7=0.f;
    #pragma unroll 2
    for (int s = 0; s < 128; s += 8) {
        a0 += p[(s+0)*DDIM]; a1 += p[(s+1)*DDIM];
        a2 += p[(s+2)*DDIM]; a3 += p[(s+3)*DDIM];
        a4 += p[(s+4)*DDIM]; a5 += p[(s+5)*DDIM];
        a6 += p[(s+6)*DDIM]; a7 += p[(s+7)*DDIM];
    }
    g_part[((size_t)(j*BATCH + b))*DDIM + d] = ((a0+a1)+(a2+a3)) + ((a4+a5)+(a6+a7));
}

// ---------------------------------------------------------------------------
// A2a: per-batch centroid. grid 128, block 256.
// ---------------------------------------------------------------------------
__global__ void __launch_bounds__(256) a2a_kernel() {
    __shared__ float sh[8];
    const int b = blockIdx.x;
    const int d = threadIdx.x;
    float a = 0.f;
    #pragma unroll
    for (int j = 0; j < 8; j++)
        a += g_part[(size_t)(j*BATCH + b)*DDIM + d];
    a *= (1.0f / (float)SEQ);
    float p = (d == 0) ? -a*a : a*a;
    float l = blocksum256(p, sh);
    float dn = rsqrtf(fmaxf(fabsf(l), 1e-8f));
    g_cb[(size_t)b*DDIM + d] = a * dn;
}

// ---------------------------------------------------------------------------
// A2b: centroid over batch -> g_mean, g_ic. single block 256.
// ---------------------------------------------------------------------------
__global__ void __launch_bounds__(256) a2b_kernel() {
    __shared__ float sh[8];
    const int d = threadIdx.x;
    float a = 0.f;
    #pragma unroll 8
    for (int b = 0; b < BATCH; b++) a += g_cb[(size_t)b*DDIM + d];
    a *= (1.0f / (float)BATCH);
    float p = (d == 0) ? -a*a : a*a;
    float l = blocksum256(p, sh);
    float dn = rsqrtf(fmaxf(fabsf(l), 1e-8f));
    float mv = a * dn;
    g_mean[d] = mv;
    if (d == 0) g_ic = 1.0f / (1.0f + mv);
}

// ---------------------------------------------------------------------------
// Pass B: per-feature Sum(t), Sum(t^2); 4 rows per warp per iteration.
// Rows row + q*QROWS, q=0..3. 8 outstanding LDG.128, one warpsum4.
// ---------------------------------------------------------------------------
__global__ void __launch_bounds__(256) passB_kernel(const float* __restrict__ x) {
    __shared__ float sS[8][DDIM];
    __shared__ float sQ[8][DDIM];
    const int lane = threadIdx.x & 31;
    const int wib  = threadIdx.x >> 5;
    const int gw   = blockIdx.x * 8 + wib;
    const int nw   = NBLK_B * 8;            // 4096 warps

    float m[8];
    {
        float4 v;
        v = reinterpret_cast<const float4*>(g_mean)[lane];    m[0]=v.x; m[1]=v.y; m[2]=v.z; m[3]=v.w;
        v = reinterpret_cast<const float4*>(g_mean)[lane+32]; m[4]=v.x; m[5]=v.y; m[6]=v.z; m[7]=v.w;
    }
    const float m0 = g_mean[0];
    const float ic = g_ic;

    float sm[8] = {0,0,0,0,0,0,0,0};
    float sq[8] = {0,0,0,0,0,0,0,0};

    for (int idx = gw; idx < QROWS; idx += nw) {
        const int row = QROWS - 1 - idx;
        const float4* rp0 = reinterpret_cast<const float4*>(x) + (size_t)row * (DDIM/4);
        const float4* rp1 = rp0 + (size_t)QROWS * (DDIM/4);
        const float4* rp2 = rp1 + (size_t)QROWS * (DDIM/4);
        const float4* rp3 = rp2 + (size_t)QROWS * (DDIM/4);
        float d0[8], d1[8], d2[8], d3[8];
        {
            float4 a = rp0[lane], b = rp0[lane+32];
            float4 c = rp1[lane], e = rp1[lane+32];
            float4 f = rp2[lane], g = rp2[lane+32];
            float4 h = rp3[lane], i = rp3[lane+32];
            d0[0]=a.x; d0[1]=a.y; d0[2]=a.z; d0[3]=a.w; d0[4]=b.x; d0[5]=b.y; d0[6]=b.z; d0[7]=b.w;
            d1[0]=c.x; d1[1]=c.y; d1[2]=c.z; d1[3]=c.w; d1[4]=e.x; d1[5]=e.y; d1[6]=e.z; d1[7]=e.w;
            d2[0]=f.x; d2[1]=f.y; d2[2]=f.z; d2[3]=f.w; d2[4]=g.x; d2[5]=g.y; d2[6]=g.z; d2[7]=g.w;
            d3[0]=h.x; d3[1]=h.y; d3[2]=h.z; d3[3]=h.w; d3[4]=i.x; d3[5]=i.y; d3[6]=i.z; d3[7]=i.w;
        }
        float p0 = m[0]*d0[0], p1 = m[0]*d1[0], p2 = m[0]*d2[0], p3 = m[0]*d3[0];
        if (lane == 0) { p0 = -p0; p1 = -p1; p2 = -p2; p3 = -p3; }
        #pragma unroll
        for (int k = 1; k < 8; k++) {
            p0 += m[k]*d0[k]; p1 += m[k]*d1[k];
            p2 += m[k]*d2[k]; p3 += m[k]*d3[k];
        }
        // broadcast time components before the reduction (independent chains)
        float x00 = __shfl_sync(0xffffffffu, d0[0], 0);
        float x01 = __shfl_sync(0xffffffffu, d1[0], 0);
        float x02 = __shfl_sync(0xffffffffu, d2[0], 0);
        float x03 = __shfl_sync(0xffffffffu, d3[0], 0);
        warpsum4(p0, p1, p2, p3);
        float al0 = fmaxf(-p0, 1.0f + 1e-7f);
        float al1 = fmaxf(-p1, 1.0f + 1e-7f);
        float al2 = fmaxf(-p2, 1.0f + 1e-7f);
        float al3 = fmaxf(-p3, 1.0f + 1e-7f);
        float f0 = acosh_over_s(al0), f1 = acosh_over_s(al1);
        float f2 = acosh_over_s(al2), f3 = acosh_over_s(al3);
        float c0 = f0 * (x00 - al0*m0) * ic;
        float c1 = f1 * (x01 - al1*m0) * ic;
        float c2 = f2 * (x02 - al2*m0) * ic;
        float c3 = f3 * (x03 - al3*m0) * ic;
        float gc0 = fmaf(f0, al0, c0), gc1 = fmaf(f1, al1, c1);
        float gc2 = fmaf(f2, al2, c2), gc3 = fmaf(f3, al3, c3);
        #pragma unroll
        for (int k = 0; k < 8; k++) {
            float t0 = fmaf(f0, d0[k], -gc0*m[k]);
            float t1 = fmaf(f1, d1[k], -gc1*m[k]);
            float t2 = fmaf(f2, d2[k], -gc2*m[k]);
            float t3 = fmaf(f3, d3[k], -gc3*m[k]);
            if (k == 0 && lane == 0) { t0 -= c0; t1 -= c1; t2 -= c2; t3 -= c3; }
            sm[k] += (t0 + t1) + (t2 + t3);
            sq[k] += fmaf(t0, t0, t1*t1) + fmaf(t2, t2, t3*t3);
        }
    }

    const int d0i = lane * 4;
    #pragma unroll
    for (int k = 0; k < 4; k++) {
        sS[wib][d0i+k]     = sm[k];   sQ[wib][d0i+k]     = sq[k];
        sS[wib][128+d0i+k] = sm[4+k]; sQ[wib][128+d0i+k] = sq[4+k];
    }
    __syncthreads();
    float accS = 0.f, accQ = 0.f;
    #pragma unroll
    for (int w = 0; w < 8; w++) { accS += sS[w][threadIdx.x]; accQ += sQ[w][threadIdx.x]; }
    g_bpS[(size_t)blockIdx.x*DDIM + threadIdx.x] = accS;
    g_bpQ[(size_t)blockIdx.x*DDIM + threadIdx.x] = accQ;
}

// ---------------------------------------------------------------------------
// finB: fold partials -> scale[d]. grid 256 (feature per block).
// ---------------------------------------------------------------------------
__global__ void __launch_bounds__(256) finB_kernel(const float* __restrict__ beta,
                                                   const float* __restrict__ gamma) {
    __shared__ float shS[8];
    __shared__ float shQ[8];
    const int d   = blockIdx.x;
    const int tid = threadIdx.x;
    const int lane = tid & 31;
    const int warp = tid >> 5;

    float s = 0.f, q = 0.f;
    #pragma unroll
    for (int i = 0; i < NBLK_B/256; i++) {
        int b = i*256 + tid;
        s += g_bpS[(size_t)b*DDIM + d];
        q += g_bpQ[(size_t)b*DDIM + d];
    }
    warpsum2(s, q);
    if (lane == 0) { shS[warp] = s; shQ[warp] = q; }
    __syncthreads();
    if (tid == 0) {
        float S = shS[0], Q = shQ[0];
        #pragma unroll
        for (int i = 1; i < 8; i++) { S += shS[i]; Q += shQ[i]; }
        const float invN = 1.0f / (float)NROWS;
        float mu  = S * invN;
        float var = Q * invN - mu*mu;
        g_scale[d] = gamma[0] * rsqrtf(var + 1e-5f);
        if (d == 0) {
            float b0 = beta[0];
            g_ib  = 1.0f / (1.0f + b0);
            g_lab = -2.0f * (1.0f + b0);
        }
    }
}

// ---------------------------------------------------------------------------
// Pass C: 4 rows loaded up front (16 outstanding LDG.128), then two
// sequential 2-row transform pipelines (keeps register peak bounded).
// ---------------------------------------------------------------------------
__global__ void __launch_bounds__(256) passC_kernel(const float* __restrict__ x,
                                                    const float* __restrict__ beta,
                                                    float* __restrict__ out) {
    const int lane = threadIdx.x & 31;
    const int gw   = (blockIdx.x * blockDim.x + threadIdx.x) >> 5;
    const int nw_  = (NBLK_C * 256) >> 5;   // 16384 warps

    float m[8], sc[8], bt[8];
    {
        float4 v;
        v = reinterpret_cast<const float4*>(g_mean)[lane];     m[0]=v.x; m[1]=v.y; m[2]=v.z; m[3]=v.w;
        v = reinterpret_cast<const float4*>(g_mean)[lane+32];  m[4]=v.x; m[5]=v.y; m[6]=v.z; m[7]=v.w;
        v = reinterpret_cast<const float4*>(g_scale)[lane];    sc[0]=v.x; sc[1]=v.y; sc[2]=v.z; sc[3]=v.w;
        v = reinterpret_cast<const float4*>(g_scale)[lane+32]; sc[4]=v.x; sc[5]=v.y; sc[6]=v.z; sc[7]=v.w;
        v = reinterpret_cast<const float4*>(beta)[lane];       bt[0]=v.x; bt[1]=v.y; bt[2]=v.z; bt[3]=v.w;
        v = reinterpret_cast<const float4*>(beta)[lane+32];    bt[4]=v.x; bt[5]=v.y; bt[6]=v.z; bt[7]=v.w;
    }
    const float m0  = g_mean[0];
    const float ic  = g_ic;
    const float ib  = g_ib;
    const float lab = g_lab;

    for (int row = gw; row < QROWS; row += nw_) {
        const float4* rp0 = reinterpret_cast<const float4*>(x) + (size_t)row * (DDIM/4);
        const float4* rp1 = rp0 + (size_t)QROWS * (DDIM/4);
        const float4* rp2 = rp1 + (size_t)QROWS * (DDIM/4);
        const float4* rp3 = rp2 + (size_t)QROWS * (DDIM/4);
        float w0[8], w1[8], w2[8], w3[8];
        {
            float4 a = __ldcs(rp0 + lane), b = __ldcs(rp0 + lane + 32);
            float4 c = __ldcs(rp1 + lane), e = __ldcs(rp1 + lane + 32);
            float4 f = __ldcs(rp2 + lane), g = __ldcs(rp2 + lane + 32);
            float4 h = __ldcs(rp3 + lane), i = __ldcs(rp3 + lane + 32);
            w0[0]=a.x; w0[1]=a.y; w0[2]=a.z; w0[3]=a.w; w0[4]=b.x; w0[5]=b.y; w0[6]=b.z; w0[7]=b.w;
            w1[0]=c.x; w1[1]=c.y; w1[2]=c.z; w1[3]=c.w; w1[4]=e.x; w1[5]=e.y; w1[6]=e.z; w1[7]=e.w;
            w2[0]=f.x; w2[1]=f.y; w2[2]=f.z; w2[3]=f.w; w2[4]=g.x; w2[5]=g.y; w2[6]=g.z; w2[7]=g.w;
            w3[0]=h.x; w3[1]=h.y; w3[2]=h.z; w3[3]=h.w; w3[4]=i.x; w3[5]=i.y; w3[6]=i.z; w3[7]=i.w;
        }

        #pragma unroll
        for (int pair = 0; pair < 2; pair++) {
            float* a = (pair == 0) ? w0 : w2;
            float* b = (pair == 0) ? w1 : w3;
            const size_t r1 = (size_t)row + (size_t)(2*pair)   * QROWS;
            const size_t r2 = (size_t)row + (size_t)(2*pair+1) * QROWS;

            // ---- t = transp0back(mean, logmap(mean, x)), scaled
            float p1 = m[0]*a[0], p2 = m[0]*b[0];
            if (lane == 0) { p1 = -p1; p2 = -p2; }
            #pragma unroll
            for (int k = 1; k < 8; k++) { p1 += m[k]*a[k]; p2 += m[k]*b[k]; }
            float x01 = __shfl_sync(0xffffffffu, a[0], 0);
            float x02 = __shfl_sync(0xffffffffu, b[0], 0);
            warpsum2(p1, p2);
            float al1 = fmaxf(-p1, 1.0f + 1e-7f);
            float al2 = fmaxf(-p2, 1.0f + 1e-7f);
            float f1 = acosh_over_s(al1);
            float f2 = acosh_over_s(al2);
            float c1 = f1 * (x01 - al1*m0) * ic;
            float c2 = f2 * (x02 - al2*m0) * ic;
            float gc1 = fmaf(f1, al1, c1);
            float gc2 = fmaf(f2, al2, c2);
            #pragma unroll
            for (int k = 0; k < 8; k++) {
                float t1 = fmaf(f1, a[k], -gc1*m[k]);
                float t2 = fmaf(f2, b[k], -gc2*m[k]);
                if (k == 0 && lane == 0) { t1 -= c1; t2 -= c2; }
                a[k] = t1 * sc[k];
                b[k] = t2 * sc[k];
            }
            float wt1 = __shfl_sync(0xffffffffu, a[0], 0);
            float wt2 = __shfl_sync(0xffffffffu, b[0], 0);

            // ---- fused: q = linner(beta,w), nw = linner(w,w)
            float q1 = bt[0]*a[0], q2 = bt[0]*b[0];
            float n1 = a[0]*a[0],  n2 = b[0]*b[0];
            if (lane == 0) { q1 = -q1; q2 = -q2; n1 = -n1; n2 = -n2; }
            #pragma unroll
            for (int k = 1; k < 8; k++) {
                q1 += bt[k]*a[k]; q2 += bt[k]*b[k];
                n1 += a[k]*a[k];  n2 += b[k]*b[k];
            }
            warpsum4(q1, n1, q2, n2);

            float cb1 = q1 * ib, cb2 = q2 * ib;
            float nn2_1 = n1 + 2.0f*cb1*(q1 - wt1) + cb1*cb1*lab;
            float nn2_2 = n2 + 2.0f*cb2*(q2 - wt2) + cb2*cb2*lab;
            float nn1 = sqrtf(fmaxf(nn2_1, 1e-7f));
            float nn2 = sqrtf(fmaxf(nn2_2, 1e-7f));
            float e1 = __expf(nn1), e2 = __expf(nn2);
            float ei1 = __frcp_rn(e1), ei2 = __frcp_rn(e2);
            float ch1 = 0.5f*(e1 + ei1), ch2 = 0.5f*(e2 + ei2);
            float sh1 = 0.5f*(e1 - ei1) * __frcp_rn(nn1);
            float sh2 = 0.5f*(e2 - ei2) * __frcp_rn(nn2);

            #pragma unroll
            for (int k = 0; k < 8; k++) {
                a[k] = fmaf(cb1, bt[k], a[k]);
                b[k] = fmaf(cb2, bt[k], b[k]);
                if (k == 0 && lane == 0) { a[0] += cb1; b[0] += cb2; }
            }

            float4* op1 = reinterpret_cast<float4*>(out) + r1 * (DDIM/4);
            float4* op2 = reinterpret_cast<float4*>(out) + r2 * (DDIM/4);
            __stcs(op1 + lane,      make_float4(fmaf(ch1,bt[0],sh1*a[0]), fmaf(ch1,bt[1],sh1*a[1]),
                                                fmaf(ch1,bt[2],sh1*a[2]), fmaf(ch1,bt[3],sh1*a[3])));
            __stcs(op1 + lane + 32, make_float4(fmaf(ch1,bt[4],sh1*a[4]), fmaf(ch1,bt[5],sh1*a[5]),
                                                fmaf(ch1,bt[6],sh1*a[6]), fmaf(ch1,bt[7],sh1*a[7])));
            __stcs(op2 + lane,      make_float4(fmaf(ch2,bt[0],sh2*b[0]), fmaf(ch2,bt[1],sh2*b[1]),
                                                fmaf(ch2,bt[2],sh2*b[2]), fmaf(ch2,bt[3],sh2*b[3])));
            __stcs(op2 + lane + 32, make_float4(fmaf(ch2,bt[4],sh2*b[4]), fmaf(ch2,bt[5],sh2*b[5]),
                                                fmaf(ch2,bt[6],sh2*b[6]), fmaf(ch2,bt[7],sh2*b[7])));
        }
    }
}

// ---------------------------------------------------------------------------
extern "C" void kernel_launch(void* const* d_in, const int* in_sizes, int n_in,
                              void* d_out, int out_size) {
    const float* x     = (const float*)d_in[0];
    const float* beta  = (const float*)d_in[1];
    const float* gamma = (const float*)d_in[2];
    float* out = (float*)d_out;

    dim3 gA(8, BATCH);
    passA_kernel<<<gA, 256>>>(x);
    a2a_kernel<<<BATCH, 256>>>();
    a2b_kernel<<<1, 256>>>();
    passB_kernel<<<NBLK_B, 256>>>(x);
    finB_kernel<<<DDIM, 256>>>(beta, gamma);
    passC_kernel<<<NBLK_C, 256>>>(x, beta, out);
}

// round 6
// speedup vs baseline: 1.0003x; 1.0003x over previous
#include <cuda_runtime.h>
#include <math.h>
#include <stdint.h>

#define DDIM   256
#define BATCH  128
#define SEQ    1024
#define NROWS  (BATCH*SEQ)          // 131072
#define HALF   (NROWS/2)            // 65536
#define NBLK_B 512
#define NBLK_C 512
#define STAGES 3

// ---- scratch (static device globals; no allocation) ----
__device__ __align__(16) float g_part[8*BATCH*DDIM];   // pass-A partials [j][b][d]
__device__ __align__(16) float g_cb[BATCH*DDIM];       // per-batch centroids
__device__ __align__(16) float g_mean[DDIM];
__device__ float g_ic;                                  // 1/(1+mean0)
__device__ __align__(16) float g_bpS[NBLK_B*DDIM];
__device__ __align__(16) float g_bpQ[NBLK_B*DDIM];
__device__ __align__(16) float g_scale[DDIM];          // gamma / sqrt(var+eps)
__device__ float g_ib;                                  // 1/(1+beta0)
__device__ float g_lab;                                 // -2(1+beta0)

__device__ __forceinline__ float warpsum(float v) {
    #pragma unroll
    for (int off = 16; off > 0; off >>= 1)
        v += __shfl_xor_sync(0xffffffffu, v, off);
    return v;
}
__device__ __forceinline__ void warpsum2(float& a, float& b) {
    #pragma unroll
    for (int off = 16; off > 0; off >>= 1) {
        a += __shfl_xor_sync(0xffffffffu, a, off);
        b += __shfl_xor_sync(0xffffffffu, b, off);
    }
}
__device__ __forceinline__ void warpsum4(float& a, float& b, float& c, float& d) {
    #pragma unroll
    for (int off = 16; off > 0; off >>= 1) {
        a += __shfl_xor_sync(0xffffffffu, a, off);
        b += __shfl_xor_sync(0xffffffffu, b, off);
        c += __shfl_xor_sync(0xffffffffu, c, off);
        d += __shfl_xor_sync(0xffffffffu, d, off);
    }
}
__device__ __forceinline__ float blocksum256(float v, float* sh) {
    const int lane = threadIdx.x & 31;
    const int warp = threadIdx.x >> 5;
    float w = warpsum(v);
    if (lane == 0) sh[warp] = w;
    __syncthreads();
    float r = sh[0];
    #pragma unroll
    for (int i = 1; i < 8; i++) r += sh[i];
    return r;
}
__device__ __forceinline__ float acosh_over_s(float alpha) {
    float a2m1 = fmaf(alpha, alpha, -1.0f);
    float r = rsqrtf(a2m1);
    float s = a2m1 * r;
    return __logf(alpha + s) * r;
}

// ---- cp.async helpers ----
__device__ __forceinline__ void cpasync16(float* smem, const float4* gmem) {
    uint32_t s = (uint32_t)__cvta_generic_to_shared(smem);
    asm volatile("cp.async.cg.shared.global [%0], [%1], 16;" :: "r"(s), "l"(gmem));
}
__device__ __forceinline__ void cpcommit() { asm volatile("cp.async.commit_group;"); }
template<int N> __device__ __forceinline__ void cpwait() {
    asm volatile("cp.async.wait_group %0;" :: "n"(N));
}

// ---------------------------------------------------------------------------
// Pass A: per-(chunk j, batch b) feature sums over 128 rows of S.
// ---------------------------------------------------------------------------
__global__ void __launch_bounds__(256) passA_kernel(const float* __restrict__ x) {
    const int j = blockIdx.x;
    const int b = blockIdx.y;
    const int d = threadIdx.x;
    const float* p = x + ((size_t)b*SEQ + (size_t)j*128) * DDIM + d;
    float a0=0.f,a1=0.f,a2=0.f,a3=0.f,a4=0.f,a5=0.f,a6=0.f,a7=0.f;
    #pragma unroll 2
    for (int s = 0; s < 128; s += 8) {
        a0 += p[(s+0)*DDIM]; a1 += p[(s+1)*DDIM];
        a2 += p[(s+2)*DDIM]; a3 += p[(s+3)*DDIM];
        a4 += p[(s+4)*DDIM]; a5 += p[(s+5)*DDIM];
        a6 += p[(s+6)*DDIM]; a7 += p[(s+7)*DDIM];
    }
    g_part[((size_t)(j*BATCH + b))*DDIM + d] = ((a0+a1)+(a2+a3)) + ((a4+a5)+(a6+a7));
}

// ---------------------------------------------------------------------------
__global__ void __launch_bounds__(256) a2a_kernel() {
    __shared__ float sh[8];
    const int b = blockIdx.x;
    const int d = threadIdx.x;
    float a = 0.f;
    #pragma unroll
    for (int j = 0; j < 8; j++)
        a += g_part[(size_t)(j*BATCH + b)*DDIM + d];
    a *= (1.0f / (float)SEQ);
    float p = (d == 0) ? -a*a : a*a;
    float l = blocksum256(p, sh);
    float dn = rsqrtf(fmaxf(fabsf(l), 1e-8f));
    g_cb[(size_t)b*DDIM + d] = a * dn;
}

__global__ void __launch_bounds__(256) a2b_kernel() {
    __shared__ float sh[8];
    const int d = threadIdx.x;
    float a = 0.f;
    #pragma unroll 8
    for (int b = 0; b < BATCH; b++) a += g_cb[(size_t)b*DDIM + d];
    a *= (1.0f / (float)BATCH);
    float p = (d == 0) ? -a*a : a*a;
    float l = blocksum256(p, sh);
    float dn = rsqrtf(fmaxf(fabsf(l), 1e-8f));
    float mv = a * dn;
    g_mean[d] = mv;
    if (d == 0) g_ic = 1.0f / (1.0f + mv);
}

// ---------------------------------------------------------------------------
// Pass B: cp.async 3-stage pipeline, 2 rows/warp/iter (rows idx, idx+HALF).
// Each lane copies+reads only its own 4×16B chunks -> per-thread wait works.
// smem: 8 warps × 3 stages × 512 floats = 48KB (sS/sQ alias it afterwards).
// ---------------------------------------------------------------------------
__global__ void __launch_bounds__(256) passB_kernel(const float* __restrict__ x) {
    __shared__ __align__(16) float pool[8*STAGES*512];   // 48KB
    const int lane = threadIdx.x & 31;
    const int wib  = threadIdx.x >> 5;
    const int gw   = blockIdx.x * 8 + wib;
    const int nw   = NBLK_B * 8;              // 4096 warps
    const int NITER = HALF / nw;              // 16 exactly

    float* wbuf = pool + wib * (STAGES*512);

    float m[8];
    {
        float4 v;
        v = reinterpret_cast<const float4*>(g_mean)[lane];    m[0]=v.x; m[1]=v.y; m[2]=v.z; m[3]=v.w;
        v = reinterpret_cast<const float4*>(g_mean)[lane+32]; m[4]=v.x; m[5]=v.y; m[6]=v.z; m[7]=v.w;
    }
    const float m0 = g_mean[0];
    const float ic = g_ic;

    float sm[8] = {0,0,0,0,0,0,0,0};
    float sq[8] = {0,0,0,0,0,0,0,0};

    // issue stage for iteration j
    auto issue = [&](int j) {
        float* s = wbuf + (j % STAGES) * 512;
        const int idx = gw + j * nw;
        const float4* p1 = reinterpret_cast<const float4*>(x) + (size_t)idx * 64;
        const float4* p2 = p1 + (size_t)HALF * 64;
        cpasync16(s + lane*4,        p1 + lane);
        cpasync16(s + 128 + lane*4,  p1 + 32 + lane);
        cpasync16(s + 256 + lane*4,  p2 + lane);
        cpasync16(s + 384 + lane*4,  p2 + 32 + lane);
    };

    issue(0); cpcommit();
    issue(1); cpcommit();
    issue(2); cpcommit();

    for (int j = 0; j < NITER; j++) {
        cpwait<STAGES-1>();
        float* s = wbuf + (j % STAGES) * 512;
        float a[8], b[8];
        {
            float4 v1 = *reinterpret_cast<float4*>(s + lane*4);
            float4 v2 = *reinterpret_cast<float4*>(s + 128 + lane*4);
            float4 u1 = *reinterpret_cast<float4*>(s + 256 + lane*4);
            float4 u2 = *reinterpret_cast<float4*>(s + 384 + lane*4);
            a[0]=v1.x; a[1]=v1.y; a[2]=v1.z; a[3]=v1.w;
            a[4]=v2.x; a[5]=v2.y; a[6]=v2.z; a[7]=v2.w;
            b[0]=u1.x; b[1]=u1.y; b[2]=u1.z; b[3]=u1.w;
            b[4]=u2.x; b[5]=u2.y; b[6]=u2.z; b[7]=u2.w;
        }
        float p1 = m[0]*a[0], p2 = m[0]*b[0];
        if (lane == 0) { p1 = -p1; p2 = -p2; }
        #pragma unroll
        for (int k = 1; k < 8; k++) { p1 += m[k]*a[k]; p2 += m[k]*b[k]; }
        float x01 = __shfl_sync(0xffffffffu, a[0], 0);
        float x02 = __shfl_sync(0xffffffffu, b[0], 0);
        warpsum2(p1, p2);
        float al1 = fmaxf(-p1, 1.0f + 1e-7f);
        float al2 = fmaxf(-p2, 1.0f + 1e-7f);
        float f1 = acosh_over_s(al1);
        float f2 = acosh_over_s(al2);
        float c1 = f1 * (x01 - al1*m0) * ic;
        float c2 = f2 * (x02 - al2*m0) * ic;
        float gc1 = fmaf(f1, al1, c1);
        float gc2 = fmaf(f2, al2, c2);
        #pragma unroll
        for (int k = 0; k < 8; k++) {
            float t1 = fmaf(f1, a[k], -gc1*m[k]);
            float t2 = fmaf(f2, b[k], -gc2*m[k]);
            if (k == 0 && lane == 0) { t1 -= c1; t2 -= c2; }
            sm[k] += t1 + t2;
            sq[k] += fmaf(t1, t1, t2*t2);
        }
        if (j + STAGES < NITER) issue(j + STAGES);
        cpcommit();                      // empty group ok -> uniform wait math
    }

    cpwait<0>();
    __syncthreads();                     // pool reuse as sS/sQ

    float (*sS)[DDIM] = reinterpret_cast<float(*)[DDIM]>(pool);
    float (*sQ)[DDIM] = reinterpret_cast<float(*)[DDIM]>(pool + 8*DDIM);
    const int d0i = lane * 4;
    #pragma unroll
    for (int k = 0; k < 4; k++) {
        sS[wib][d0i+k]     = sm[k];   sQ[wib][d0i+k]     = sq[k];
        sS[wib][128+d0i+k] = sm[4+k]; sQ[wib][128+d0i+k] = sq[4+k];
    }
    __syncthreads();
    float accS = 0.f, accQ = 0.f;
    #pragma unroll
    for (int w = 0; w < 8; w++) { accS += sS[w][threadIdx.x]; accQ += sQ[w][threadIdx.x]; }
    g_bpS[(size_t)blockIdx.x*DDIM + threadIdx.x] = accS;
    g_bpQ[(size_t)blockIdx.x*DDIM + threadIdx.x] = accQ;
}

// ---------------------------------------------------------------------------
__global__ void __launch_bounds__(256) finB_kernel(const float* __restrict__ beta,
                                                   const float* __restrict__ gamma) {
    __shared__ float shS[8];
    __shared__ float shQ[8];
    const int d   = blockIdx.x;
    const int tid = threadIdx.x;
    const int lane = tid & 31;
    const int warp = tid >> 5;

    float s = 0.f, q = 0.f;
    #pragma unroll
    for (int i = 0; i < NBLK_B/256; i++) {
        int b = i*256 + tid;
        s += g_bpS[(size_t)b*DDIM + d];
        q += g_bpQ[(size_t)b*DDIM + d];
    }
    warpsum2(s, q);
    if (lane == 0) { shS[warp] = s; shQ[warp] = q; }
    __syncthreads();
    if (tid == 0) {
        float S = shS[0], Q = shQ[0];
        #pragma unroll
        for (int i = 1; i < 8; i++) { S += shS[i]; Q += shQ[i]; }
        const float invN = 1.0f / (float)NROWS;
        float mu  = S * invN;
        float var = Q * invN - mu*mu;
        g_scale[d] = gamma[0] * rsqrtf(var + 1e-5f);
        if (d == 0) {
            float b0 = beta[0];
            g_ib  = 1.0f / (1.0f + b0);
            g_lab = -2.0f * (1.0f + b0);
        }
    }
}

// ---------------------------------------------------------------------------
// Pass C: cp.async 3-stage pipeline, 2 rows/warp/iter, full transform + store.
// ---------------------------------------------------------------------------
__global__ void __launch_bounds__(256) passC_kernel(const float* __restrict__ x,
                                                    const float* __restrict__ beta,
                                                    float* __restrict__ out) {
    __shared__ __align__(16) float pool[8*STAGES*512];   // 48KB
    const int lane = threadIdx.x & 31;
    const int wib  = threadIdx.x >> 5;
    const int gw   = blockIdx.x * 8 + wib;
    const int nw   = NBLK_C * 8;              // 4096 warps
    const int NITER = HALF / nw;              // 16 exactly

    float* wbuf = pool + wib * (STAGES*512);

    float m[8], sc[8], bt[8];
    {
        float4 v;
        v = reinterpret_cast<const float4*>(g_mean)[lane];     m[0]=v.x; m[1]=v.y; m[2]=v.z; m[3]=v.w;
        v = reinterpret_cast<const float4*>(g_mean)[lane+32];  m[4]=v.x; m[5]=v.y; m[6]=v.z; m[7]=v.w;
        v = reinterpret_cast<const float4*>(g_scale)[lane];    sc[0]=v.x; sc[1]=v.y; sc[2]=v.z; sc[3]=v.w;
        v = reinterpret_cast<const float4*>(g_scale)[lane+32]; sc[4]=v.x; sc[5]=v.y; sc[6]=v.z; sc[7]=v.w;
        v = reinterpret_cast<const float4*>(beta)[lane];       bt[0]=v.x; bt[1]=v.y; bt[2]=v.z; bt[3]=v.w;
        v = reinterpret_cast<const float4*>(beta)[lane+32];    bt[4]=v.x; bt[5]=v.y; bt[6]=v.z; bt[7]=v.w;
    }
    const float m0  = g_mean[0];
    const float ic  = g_ic;
    const float ib  = g_ib;
    const float lab = g_lab;

    auto issue = [&](int j) {
        float* s = wbuf + (j % STAGES) * 512;
        const int idx = gw + j * nw;
        const float4* p1 = reinterpret_cast<const float4*>(x) + (size_t)idx * 64;
        const float4* p2 = p1 + (size_t)HALF * 64;
        cpasync16(s + lane*4,        p1 + lane);
        cpasync16(s + 128 + lane*4,  p1 + 32 + lane);
        cpasync16(s + 256 + lane*4,  p2 + lane);
        cpasync16(s + 384 + lane*4,  p2 + 32 + lane);
    };

    issue(0); cpcommit();
    issue(1); cpcommit();
    issue(2); cpcommit();

    for (int j = 0; j < NITER; j++) {
        cpwait<STAGES-1>();
        float* s = wbuf + (j % STAGES) * 512;
        const int idx = gw + j * nw;
        float a[8], b[8];
        {
            float4 v1 = *reinterpret_cast<float4*>(s + lane*4);
            float4 v2 = *reinterpret_cast<float4*>(s + 128 + lane*4);
            float4 u1 = *reinterpret_cast<float4*>(s + 256 + lane*4);
            float4 u2 = *reinterpret_cast<float4*>(s + 384 + lane*4);
            a[0]=v1.x; a[1]=v1.y; a[2]=v1.z; a[3]=v1.w;
            a[4]=v2.x; a[5]=v2.y; a[6]=v2.z; a[7]=v2.w;
            b[0]=u1.x; b[1]=u1.y; b[2]=u1.z; b[3]=u1.w;
            b[4]=u2.x; b[5]=u2.y; b[6]=u2.z; b[7]=u2.w;
        }
        // ---- t = transp0back(mean, logmap(mean, x)), scaled
        float p1 = m[0]*a[0], p2 = m[0]*b[0];
        if (lane == 0) { p1 = -p1; p2 = -p2; }
        #pragma unroll
        for (int k = 1; k < 8; k++) { p1 += m[k]*a[k]; p2 += m[k]*b[k]; }
        float x01 = __shfl_sync(0xffffffffu, a[0], 0);
        float x02 = __shfl_sync(0xffffffffu, b[0], 0);
        warpsum2(p1, p2);
        float al1 = fmaxf(-p1, 1.0f + 1e-7f);
        float al2 = fmaxf(-p2, 1.0f + 1e-7f);
        float f1 = acosh_over_s(al1);
        float f2 = acosh_over_s(al2);
        float c1 = f1 * (x01 - al1*m0) * ic;
        float c2 = f2 * (x02 - al2*m0) * ic;
        float gc1 = fmaf(f1, al1, c1);
        float gc2 = fmaf(f2, al2, c2);
        #pragma unroll
        for (int k = 0; k < 8; k++) {
            float t1 = fmaf(f1, a[k], -gc1*m[k]);
            float t2 = fmaf(f2, b[k], -gc2*m[k]);
            if (k == 0 && lane == 0) { t1 -= c1; t2 -= c2; }
            a[k] = t1 * sc[k];
            b[k] = t2 * sc[k];
        }
        float wt1 = __shfl_sync(0xffffffffu, a[0], 0);
        float wt2 = __shfl_sync(0xffffffffu, b[0], 0);

        // ---- fused: q = linner(beta,w), n = linner(w,w)
        float q1 = bt[0]*a[0], q2 = bt[0]*b[0];
        float n1 = a[0]*a[0],  n2 = b[0]*b[0];
        if (lane == 0) { q1 = -q1; q2 = -q2; n1 = -n1; n2 = -n2; }
        #pragma unroll
        for (int k = 1; k < 8; k++) {
            q1 += bt[k]*a[k]; q2 += bt[k]*b[k];
            n1 += a[k]*a[k];  n2 += b[k]*b[k];
        }
        warpsum4(q1, n1, q2, n2);

        float cb1 = q1 * ib, cb2 = q2 * ib;
        float nn2_1 = n1 + 2.0f*cb1*(q1 - wt1) + cb1*cb1*lab;
        float nn2_2 = n2 + 2.0f*cb2*(q2 - wt2) + cb2*cb2*lab;
        float nn1 = sqrtf(fmaxf(nn2_1, 1e-7f));
        float nn2 = sqrtf(fmaxf(nn2_2, 1e-7f));
        float e1 = __expf(nn1), e2 = __expf(nn2);
        float ei1 = __frcp_rn(e1), ei2 = __frcp_rn(e2);
        float ch1 = 0.5f*(e1 + ei1), ch2 = 0.5f*(e2 + ei2);
        float sh1 = 0.5f*(e1 - ei1) * __frcp_rn(nn1);
        float sh2 = 0.5f*(e2 - ei2) * __frcp_rn(nn2);

        #pragma unroll
        for (int k = 0; k < 8; k++) {
            a[k] = fmaf(cb1, bt[k], a[k]);
            b[k] = fmaf(cb2, bt[k], b[k]);
            if (k == 0 && lane == 0) { a[0] += cb1; b[0] += cb2; }
        }

        float4* op1 = reinterpret_cast<float4*>(out) + (size_t)idx * 64;
        float4* op2 = op1 + (size_t)HALF * 64;
        __stcs(op1 + lane,      make_float4(fmaf(ch1,bt[0],sh1*a[0]), fmaf(ch1,bt[1],sh1*a[1]),
                                            fmaf(ch1,bt[2],sh1*a[2]), fmaf(ch1,bt[3],sh1*a[3])));
        __stcs(op1 + lane + 32, make_float4(fmaf(ch1,bt[4],sh1*a[4]), fmaf(ch1,bt[5],sh1*a[5]),
                                            fmaf(ch1,bt[6],sh1*a[6]), fmaf(ch1,bt[7],sh1*a[7])));
        __stcs(op2 + lane,      make_float4(fmaf(ch2,bt[0],sh2*b[0]), fmaf(ch2,bt[1],sh2*b[1]),
                                            fmaf(ch2,bt[2],sh2*b[2]), fmaf(ch2,bt[3],sh2*b[3])));
        __stcs(op2 + lane + 32, make_float4(fmaf(ch2,bt[4],sh2*b[4]), fmaf(ch2,bt[5],sh2*b[5]),
                                            fmaf(ch2,bt[6],sh2*b[6]), fmaf(ch2,bt[7],sh2*b[7])));

        if (j + STAGES < NITER) issue(j + STAGES);
        cpcommit();
    }
}

// ---------------------------------------------------------------------------
extern "C" void kernel_launch(void* const* d_in, const int* in_sizes, int n_in,
                              void* d_out, int out_size) {
    const float* x     = (const float*)d_in[0];
    const float* beta  = (const float*)d_in[1];
    const float* gamma = (const float*)d_in[2];
    float* out = (float*)d_out;

    dim3 gA(8, BATCH);
    passA_kernel<<<gA, 256>>>(x);
    a2a_kernel<<<BATCH, 256>>>();
    a2b_kernel<<<1, 256>>>();
    passB_kernel<<<NBLK_B, 256>>>(x);
    finB_kernel<<<DDIM, 256>>>(beta, gamma);
    passC_kernel<<<NBLK_C, 256>>>(x, beta, out);
}

// round 7
// speedup vs baseline: 1.0755x; 1.0752x over previous
#include <cuda_runtime.h>
#include <math.h>

#define DDIM   256
#define BATCH  128
#define SEQ    1024
#define NROWS  (BATCH*SEQ)          // 131072
#define HALF   (NROWS/2)            // 65536
#define NBLK_B 512
#define NBLK_C 2048

// ---- scratch (static device globals; no allocation) ----
__device__ __align__(16) float g_part[8*BATCH*DDIM];   // pass-A partials [j][b][d]
__device__ __align__(16) float g_cb[BATCH*DDIM];       // per-batch centroids
__device__ __align__(16) float g_mean[DDIM];
__device__ float g_ic;                                  // 1/(1+mean0)
__device__ __align__(16) float g_bpS[NBLK_B*DDIM];
__device__ __align__(16) float g_bpQ[NBLK_B*DDIM];
__device__ __align__(16) float g_scale[DDIM];          // gamma / sqrt(var+eps)
__device__ float g_ib;                                  // 1/(1+beta0)
__device__ float g_lab;                                 // -2(1+beta0)
__device__ __align__(16) float4 g_rowsc[NROWS];        // per-row (f, gc, c, 0)

__device__ __forceinline__ float warpsum(float v) {
    #pragma unroll
    for (int off = 16; off > 0; off >>= 1)
        v += __shfl_xor_sync(0xffffffffu, v, off);
    return v;
}
__device__ __forceinline__ void warpsum2(float& a, float& b) {
    #pragma unroll
    for (int off = 16; off > 0; off >>= 1) {
        a += __shfl_xor_sync(0xffffffffu, a, off);
        b += __shfl_xor_sync(0xffffffffu, b, off);
    }
}
__device__ __forceinline__ void warpsum4(float& a, float& b, float& c, float& d) {
    #pragma unroll
    for (int off = 16; off > 0; off >>= 1) {
        a += __shfl_xor_sync(0xffffffffu, a, off);
        b += __shfl_xor_sync(0xffffffffu, b, off);
        c += __shfl_xor_sync(0xffffffffu, c, off);
        d += __shfl_xor_sync(0xffffffffu, d, off);
    }
}
__device__ __forceinline__ float blocksum256(float v, float* sh) {
    const int lane = threadIdx.x & 31;
    const int warp = threadIdx.x >> 5;
    float w = warpsum(v);
    if (lane == 0) sh[warp] = w;
    __syncthreads();
    float r = sh[0];
    #pragma unroll
    for (int i = 1; i < 8; i++) r += sh[i];
    return r;
}
__device__ __forceinline__ float acosh_over_s(float alpha) {
    float a2m1 = fmaf(alpha, alpha, -1.0f);
    float r = rsqrtf(a2m1);
    float s = a2m1 * r;
    return __logf(alpha + s) * r;
}

// ---------------------------------------------------------------------------
// Pass A: per-(chunk j, batch b) feature sums over 128 rows of S.
// ---------------------------------------------------------------------------
__global__ void __launch_bounds__(256) passA_kernel(const float* __restrict__ x) {
    const int j = blockIdx.x;
    const int b = blockIdx.y;
    const int d = threadIdx.x;
    const float* p = x + ((size_t)b*SEQ + (size_t)j*128) * DDIM + d;
    float a0=0.f,a1=0.f,a2=0.f,a3=0.f,a4=0.f,a5=0.f,a6=0.f,a7=0.f;
    #pragma unroll 2
    for (int s = 0; s < 128; s += 8) {
        a0 += p[(s+0)*DDIM]; a1 += p[(s+1)*DDIM];
        a2 += p[(s+2)*DDIM]; a3 += p[(s+3)*DDIM];
        a4 += p[(s+4)*DDIM]; a5 += p[(s+5)*DDIM];
        a6 += p[(s+6)*DDIM]; a7 += p[(s+7)*DDIM];
    }
    g_part[((size_t)(j*BATCH + b))*DDIM + d] = ((a0+a1)+(a2+a3)) + ((a4+a5)+(a6+a7));
}

// ---------------------------------------------------------------------------
__global__ void __launch_bounds__(256) a2a_kernel() {
    __shared__ float sh[8];
    const int b = blockIdx.x;
    const int d = threadIdx.x;
    float a = 0.f;
    #pragma unroll
    for (int j = 0; j < 8; j++)
        a += g_part[(size_t)(j*BATCH + b)*DDIM + d];
    a *= (1.0f / (float)SEQ);
    float p = (d == 0) ? -a*a : a*a;
    float l = blocksum256(p, sh);
    float dn = rsqrtf(fmaxf(fabsf(l), 1e-8f));
    g_cb[(size_t)b*DDIM + d] = a * dn;
}

__global__ void __launch_bounds__(256) a2b_kernel() {
    __shared__ float sh[8];
    const int d = threadIdx.x;
    float a = 0.f;
    #pragma unroll 8
    for (int b = 0; b < BATCH; b++) a += g_cb[(size_t)b*DDIM + d];
    a *= (1.0f / (float)BATCH);
    float p = (d == 0) ? -a*a : a*a;
    float l = blocksum256(p, sh);
    float dn = rsqrtf(fmaxf(fabsf(l), 1e-8f));
    float mv = a * dn;
    g_mean[d] = mv;
    if (d == 0) g_ic = 1.0f / (1.0f + mv);
}

// ---------------------------------------------------------------------------
// Pass B: per-feature Sum(t), Sum(t^2); 2 rows/warp (idx, idx+HALF),
// descending. ALSO stores per-row scalars (f, gc, c) for pass C reuse.
// ---------------------------------------------------------------------------
__global__ void __launch_bounds__(256) passB_kernel(const float* __restrict__ x) {
    __shared__ float sS[8][DDIM];
    __shared__ float sQ[8][DDIM];
    const int lane = threadIdx.x & 31;
    const int wib  = threadIdx.x >> 5;
    const int gw   = blockIdx.x * 8 + wib;
    const int nw   = NBLK_B * 8;

    float m[8];
    {
        float4 v;
        v = reinterpret_cast<const float4*>(g_mean)[lane];    m[0]=v.x; m[1]=v.y; m[2]=v.z; m[3]=v.w;
        v = reinterpret_cast<const float4*>(g_mean)[lane+32]; m[4]=v.x; m[5]=v.y; m[6]=v.z; m[7]=v.w;
    }
    const float m0 = g_mean[0];
    const float ic = g_ic;

    float sm[8] = {0,0,0,0,0,0,0,0};
    float sq[8] = {0,0,0,0,0,0,0,0};

    for (int idx = gw; idx < HALF; idx += nw) {
        const int row = HALF - 1 - idx;            // descending
        const float4* rp1 = reinterpret_cast<const float4*>(x) + (size_t)row * (DDIM/4);
        const float4* rp2 = rp1 + (size_t)HALF * (DDIM/4);
        float a[8], b[8];
        {
            float4 v1 = rp1[lane], v2 = rp1[lane+32];
            float4 w1 = rp2[lane], w2 = rp2[lane+32];
            a[0]=v1.x; a[1]=v1.y; a[2]=v1.z; a[3]=v1.w;
            a[4]=v2.x; a[5]=v2.y; a[6]=v2.z; a[7]=v2.w;
            b[0]=w1.x; b[1]=w1.y; b[2]=w1.z; b[3]=w1.w;
            b[4]=w2.x; b[5]=w2.y; b[6]=w2.z; b[7]=w2.w;
        }
        float p1 = m[0]*a[0], p2 = m[0]*b[0];
        if (lane == 0) { p1 = -p1; p2 = -p2; }
        #pragma unroll
        for (int k = 1; k < 8; k++) { p1 += m[k]*a[k]; p2 += m[k]*b[k]; }
        float x01 = __shfl_sync(0xffffffffu, a[0], 0);
        float x02 = __shfl_sync(0xffffffffu, b[0], 0);
        warpsum2(p1, p2);
        float al1 = fmaxf(-p1, 1.0f + 1e-7f);
        float al2 = fmaxf(-p2, 1.0f + 1e-7f);
        float f1 = acosh_over_s(al1);
        float f2 = acosh_over_s(al2);
        float c1 = f1 * (x01 - al1*m0) * ic;
        float c2 = f2 * (x02 - al2*m0) * ic;
        float gc1 = fmaf(f1, al1, c1);
        float gc2 = fmaf(f2, al2, c2);
        if (lane == 0) {
            g_rowsc[row]        = make_float4(f1, gc1, c1, 0.f);
            g_rowsc[row + HALF] = make_float4(f2, gc2, c2, 0.f);
        }
        #pragma unroll
        for (int k = 0; k < 8; k++) {
            float t1 = fmaf(f1, a[k], -gc1*m[k]);
            float t2 = fmaf(f2, b[k], -gc2*m[k]);
            if (k == 0 && lane == 0) { t1 -= c1; t2 -= c2; }
            sm[k] += t1 + t2;
            sq[k] += fmaf(t1, t1, t2*t2);
        }
    }

    const int d0i = lane * 4;
    #pragma unroll
    for (int k = 0; k < 4; k++) {
        sS[wib][d0i+k]     = sm[k];   sQ[wib][d0i+k]     = sq[k];
        sS[wib][128+d0i+k] = sm[4+k]; sQ[wib][128+d0i+k] = sq[4+k];
    }
    __syncthreads();
    float accS = 0.f, accQ = 0.f;
    #pragma unroll
    for (int w = 0; w < 8; w++) { accS += sS[w][threadIdx.x]; accQ += sQ[w][threadIdx.x]; }
    g_bpS[(size_t)blockIdx.x*DDIM + threadIdx.x] = accS;
    g_bpQ[(size_t)blockIdx.x*DDIM + threadIdx.x] = accQ;
}

// ---------------------------------------------------------------------------
__global__ void __launch_bounds__(256) finB_kernel(const float* __restrict__ beta,
                                                   const float* __restrict__ gamma) {
    __shared__ float shS[8];
    __shared__ float shQ[8];
    const int d   = blockIdx.x;
    const int tid = threadIdx.x;
    const int lane = tid & 31;
    const int warp = tid >> 5;

    float s = 0.f, q = 0.f;
    #pragma unroll
    for (int i = 0; i < NBLK_B/256; i++) {
        int b = i*256 + tid;
        s += g_bpS[(size_t)b*DDIM + d];
        q += g_bpQ[(size_t)b*DDIM + d];
    }
    warpsum2(s, q);
    if (lane == 0) { shS[warp] = s; shQ[warp] = q; }
    __syncthreads();
    if (tid == 0) {
        float S = shS[0], Q = shQ[0];
        #pragma unroll
        for (int i = 1; i < 8; i++) { S += shS[i]; Q += shQ[i]; }
        const float invN = 1.0f / (float)NROWS;
        float mu  = S * invN;
        float var = Q * invN - mu*mu;
        g_scale[d] = gamma[0] * rsqrtf(var + 1e-5f);
        if (d == 0) {
            float b0 = beta[0];
            g_ib  = 1.0f / (1.0f + b0);
            g_lab = -2.0f * (1.0f + b0);
        }
    }
}

// ---------------------------------------------------------------------------
// Pass C: REUSES per-row (f, gc, c) from pass B — no dot/warpsum/acosh chain.
// t_k = f*x_k - gc*m_k (- c on time comp); then scale, transport, expmap.
// ---------------------------------------------------------------------------
__global__ void __launch_bounds__(256) passC_kernel(const float* __restrict__ x,
                                                    const float* __restrict__ beta,
                                                    float* __restrict__ out) {
    const int lane = threadIdx.x & 31;
    const int gw   = (blockIdx.x * blockDim.x + threadIdx.x) >> 5;
    const int nw_  = (NBLK_C * 256) >> 5;   // 16384 warps

    float m[8], sc[8], bt[8];
    {
        float4 v;
        v = reinterpret_cast<const float4*>(g_mean)[lane];     m[0]=v.x; m[1]=v.y; m[2]=v.z; m[3]=v.w;
        v = reinterpret_cast<const float4*>(g_mean)[lane+32];  m[4]=v.x; m[5]=v.y; m[6]=v.z; m[7]=v.w;
        v = reinterpret_cast<const float4*>(g_scale)[lane];    sc[0]=v.x; sc[1]=v.y; sc[2]=v.z; sc[3]=v.w;
        v = reinterpret_cast<const float4*>(g_scale)[lane+32]; sc[4]=v.x; sc[5]=v.y; sc[6]=v.z; sc[7]=v.w;
        v = reinterpret_cast<const float4*>(beta)[lane];       bt[0]=v.x; bt[1]=v.y; bt[2]=v.z; bt[3]=v.w;
        v = reinterpret_cast<const float4*>(beta)[lane+32];    bt[4]=v.x; bt[5]=v.y; bt[6]=v.z; bt[7]=v.w;
    }
    const float ib  = g_ib;
    const float lab = g_lab;

    for (int row = gw; row < HALF; row += nw_) {
        const float4* rp1 = reinterpret_cast<const float4*>(x) + (size_t)row * (DDIM/4);
        const float4* rp2 = rp1 + (size_t)HALF * (DDIM/4);
        float a[8], b[8];
        {
            float4 v1 = __ldcs(rp1 + lane), v2 = __ldcs(rp1 + lane + 32);
            float4 u1 = __ldcs(rp2 + lane), u2 = __ldcs(rp2 + lane + 32);
            a[0]=v1.x; a[1]=v1.y; a[2]=v1.z; a[3]=v1.w;
            a[4]=v2.x; a[5]=v2.y; a[6]=v2.z; a[7]=v2.w;
            b[0]=u1.x; b[1]=u1.y; b[2]=u1.z; b[3]=u1.w;
            b[4]=u2.x; b[5]=u2.y; b[6]=u2.z; b[7]=u2.w;
        }
        const float4 s1 = __ldg(&g_rowsc[row]);
        const float4 s2 = __ldg(&g_rowsc[row + HALF]);
        const float f1 = s1.x, gc1 = s1.y, c1 = s1.z;
        const float f2 = s2.x, gc2 = s2.y, c2 = s2.z;

        // t scaled
        #pragma unroll
        for (int k = 0; k < 8; k++) {
            float t1 = fmaf(f1, a[k], -gc1*m[k]);
            float t2 = fmaf(f2, b[k], -gc2*m[k]);
            if (k == 0 && lane == 0) { t1 -= c1; t2 -= c2; }
            a[k] = t1 * sc[k];
            b[k] = t2 * sc[k];
        }
        float wt1 = __shfl_sync(0xffffffffu, a[0], 0);
        float wt2 = __shfl_sync(0xffffffffu, b[0], 0);

        // fused: q = linner(beta,w), n = linner(w,w)
        float q1 = bt[0]*a[0], q2 = bt[0]*b[0];
        float n1 = a[0]*a[0],  n2 = b[0]*b[0];
        if (lane == 0) { q1 = -q1; q2 = -q2; n1 = -n1; n2 = -n2; }
        #pragma unroll
        for (int k = 1; k < 8; k++) {
            q1 += bt[k]*a[k]; q2 += bt[k]*b[k];
            n1 += a[k]*a[k];  n2 += b[k]*b[k];
        }
        warpsum4(q1, n1, q2, n2);

        float cb1 = q1 * ib, cb2 = q2 * ib;
        float nn2_1 = n1 + 2.0f*cb1*(q1 - wt1) + cb1*cb1*lab;
        float nn2_2 = n2 + 2.0f*cb2*(q2 - wt2) + cb2*cb2*lab;
        float nn1 = sqrtf(fmaxf(nn2_1, 1e-7f));
        float nn2 = sqrtf(fmaxf(nn2_2, 1e-7f));
        float e1 = __expf(nn1), e2 = __expf(nn2);
        float ei1 = __frcp_rn(e1), ei2 = __frcp_rn(e2);
        float ch1 = 0.5f*(e1 + ei1), ch2 = 0.5f*(e2 + ei2);
        float sh1 = 0.5f*(e1 - ei1) * __frcp_rn(nn1);
        float sh2 = 0.5f*(e2 - ei2) * __frcp_rn(nn2);

        #pragma unroll
        for (int k = 0; k < 8; k++) {
            a[k] = fmaf(cb1, bt[k], a[k]);
            b[k] = fmaf(cb2, bt[k], b[k]);
            if (k == 0 && lane == 0) { a[0] += cb1; b[0] += cb2; }
        }

        float4* op1 = reinterpret_cast<float4*>(out) + (size_t)row * (DDIM/4);
        float4* op2 = op1 + (size_t)HALF * (DDIM/4);
        __stcs(op1 + lane,      make_float4(fmaf(ch1,bt[0],sh1*a[0]), fmaf(ch1,bt[1],sh1*a[1]),
                                            fmaf(ch1,bt[2],sh1*a[2]), fmaf(ch1,bt[3],sh1*a[3])));
        __stcs(op1 + lane + 32, make_float4(fmaf(ch1,bt[4],sh1*a[4]), fmaf(ch1,bt[5],sh1*a[5]),
                                            fmaf(ch1,bt[6],sh1*a[6]), fmaf(ch1,bt[7],sh1*a[7])));
        __stcs(op2 + lane,      make_float4(fmaf(ch2,bt[0],sh2*b[0]), fmaf(ch2,bt[1],sh2*b[1]),
                                            fmaf(ch2,bt[2],sh2*b[2]), fmaf(ch2,bt[3],sh2*b[3])));
        __stcs(op2 + lane + 32, make_float4(fmaf(ch2,bt[4],sh2*b[4]), fmaf(ch2,bt[5],sh2*b[5]),
                                            fmaf(ch2,bt[6],sh2*b[6]), fmaf(ch2,bt[7],sh2*b[7])));
    }
}

// ---------------------------------------------------------------------------
extern "C" void kernel_launch(void* const* d_in, const int* in_sizes, int n_in,
                              void* d_out, int out_size) {
    const float* x     = (const float*)d_in[0];
    const float* beta  = (const float*)d_in[1];
    const float* gamma = (const float*)d_in[2];
    float* out = (float*)d_out;

    dim3 gA(8, BATCH);
    passA_kernel<<<gA, 256>>>(x);
    a2a_kernel<<<BATCH, 256>>>();
    a2b_kernel<<<1, 256>>>();
    passB_kernel<<<NBLK_B, 256>>>(x);
    finB_kernel<<<DDIM, 256>>>(beta, gamma);
    passC_kernel<<<NBLK_C, 256>>>(x, beta, out);
}